// round 10
// baseline (speedup 1.0000x reference)
#include <cuda_runtime.h>
#include <cuda_bf16.h>
#include <cstdint>
#include <cstddef>

#define MAXNNZ 40
#define BG 256
#define SLICE 25165824UL   // 768*256*128 floats (largest N*B*F slab)

// Wc offsets (floats): d1 512x512, d2 256x256, d3 128x128, out 32x4
#define W1OFF 0
#define W2OFF 262144
#define W3OFF 327680
#define W4OFF 344064

// ---------------- static scratch (no allocation allowed) ----------------
__device__ float g_A[SLICE];                 // ping buffer (N,B,F)
__device__ float g_B[SLICE];                 // pong buffer
__device__ float g_Z[3*SLICE];               // Chebyshev / Horner temporaries
__device__ float g_S3[768*256*64];           // skip s3
__device__ float g_S2[192*256*128];          // skip s2
__device__ float g_S1[48*256*256];           // skip s1
__device__ float g_Wc[360448];               // combined Horner weights (all layers)
__device__ int   g_cidx[4*768*MAXNNZ];       // ELL col indices per level
__device__ float g_cval[4*768*MAXNNZ];       // ELL values
__device__ int   g_cnnz[4*768];              // per-row nnz
__device__ float g_sum[8*256];               // BN channel sums (per layer)
__device__ float g_sq[8*256];                // BN channel sum-of-squares

// ---------------- small kernels ----------------

__global__ void zero_all_k(float* s, float* q) {
    int i = blockIdx.x * blockDim.x + threadIdx.x;
    s[i] = 0.f; q[i] = 0.f;
}

__global__ void build_all_k(const float* __restrict__ L3, const float* __restrict__ L2,
                            const float* __restrict__ L1, const float* __restrict__ L0,
                            int* __restrict__ idx, float* __restrict__ val,
                            int* __restrict__ nnz) {
    int t = blockIdx.x * blockDim.x + threadIdx.x;
    if (t >= 1020) return;
    int lvl, n, N;
    const float* L;
    if (t < 768)       { lvl = 0; n = t;        N = 768; L = L3; }
    else if (t < 960)  { lvl = 1; n = t - 768;  N = 192; L = L2; }
    else if (t < 1008) { lvl = 2; n = t - 960;  N = 48;  L = L1; }
    else               { lvl = 3; n = t - 1008; N = 12;  L = L0; }
    int base = (lvl * 768 + n) * MAXNNZ;
    int c = 0;
    for (int m = 0; m < N; m++) {
        float v = L[n * N + m];
        if (v != 0.0f && c < MAXNNZ) {
            idx[base + c] = m;
            val[base + c] = v;
            c++;
        }
    }
    nnz[lvl * 768 + n] = c;
}

// x (4,8,8,8,768) -> A layout (n, bg, c) with bg = b0*64 + hw
__global__ void transpose_in_k(const float* __restrict__ x, float* __restrict__ A) {
    int t = blockIdx.x * blockDim.x + threadIdx.x;
    int n = t % 768;
    int r = t / 768;
    int hw = r & 63; r >>= 6;
    int c = r & 7;  int b0 = r >> 3;
    A[((size_t)n * BG + (size_t)b0 * 64 + hw) * 8 + c] = x[t];
}

// All Horner weight combos in one launch.
__global__ void wcomb_all_k(const float* __restrict__ w1, const float* __restrict__ w2,
                            const float* __restrict__ w3, const float* __restrict__ w4,
                            float* __restrict__ wc) {
    int i = blockIdx.x * blockDim.x + threadIdx.x;
    const float* w; int Fo, off, r, FFo;
    if (i < 65536)      { w = w1; Fo = 128; off = W1OFF; r = i;         FFo = 65536; }
    else if (i < 81920) { w = w2; Fo = 64;  off = W2OFF; r = i - 65536; FFo = 16384; }
    else if (i < 86016) { w = w3; Fo = 32;  off = W3OFF; r = i - 81920; FFo = 4096;  }
    else if (i < 86048) { w = w4; Fo = 1;   off = W4OFF; r = i - 86016; FFo = 32;    }
    else return;
    int k = r / Fo, n = r - (r / Fo) * Fo;
    float w0 = w[r], wa = w[FFo + r], wb = w[2 * FFo + r], wd = w[3 * FFo + r];
    float* row = wc + off + (size_t)k * 4 * Fo + n;
    row[0]      = 4.f * wd;
    row[Fo]     = 2.f * wb;
    row[2 * Fo] = wa - 3.f * wd;
    row[3 * Fo] = w0 - wb;
}

// ---------------- fused node-resident Chebyshev kernels ----------------
// Invariant: N * colt4 == 3072 for every level (768*4, 192*16, 48*64, 12*256).
// A block holds the ENTIRE node dimension for its column tile in smem,
// so all three L-applications gather from smem instead of L2.

// Encoder: x1 = L x0; x2 = 2 L x1 - x0; x3 = 2 L x2 - x1.  Writes x1,x2,x3
// to Zb + {0,1,2}*SLICE.
__global__ __launch_bounds__(256) void cheb3_enc_k(
        const int* __restrict__ idx, const float* __restrict__ val,
        const int* __restrict__ nnz, int cols4, int lgc,
        const float4* __restrict__ X, float* __restrict__ Zb) {
    extern __shared__ float4 sm[];
    float4* b0 = sm;
    float4* b1 = sm + 3072;
    int colt4 = 1 << lgc;
    int c0 = blockIdx.x << lgc;
    int tid = threadIdx.x;
    float4* Z0 = (float4*)Zb;
    float4* Z1 = (float4*)(Zb + SLICE);
    float4* Z2 = (float4*)(Zb + 2 * SLICE);

    for (int e = tid; e < 3072; e += 256) {
        int row = e >> lgc, cc = e & (colt4 - 1);
        b0[e] = X[(size_t)row * cols4 + c0 + cc];
    }
    __syncthreads();
    // pass1: x1 = L x0
    for (int e = tid; e < 3072; e += 256) {
        int row = e >> lgc, cc = e & (colt4 - 1);
        const int* ip = idx + row * MAXNNZ;
        const float* vp = val + row * MAXNNZ;
        int nn = nnz[row];
        float4 a = make_float4(0.f, 0.f, 0.f, 0.f);
        #pragma unroll 4
        for (int j = 0; j < nn; j++) {
            float v = vp[j];
            float4 xv = b0[(ip[j] << lgc) + cc];
            a.x += v * xv.x; a.y += v * xv.y; a.z += v * xv.z; a.w += v * xv.w;
        }
        b1[e] = a;
        Z0[(size_t)row * cols4 + c0 + cc] = a;
    }
    __syncthreads();
    // pass2: x2 = 2 L x1 - x0 (in-place over b0; own-row read only)
    for (int e = tid; e < 3072; e += 256) {
        int row = e >> lgc, cc = e & (colt4 - 1);
        const int* ip = idx + row * MAXNNZ;
        const float* vp = val + row * MAXNNZ;
        int nn = nnz[row];
        float4 a = make_float4(0.f, 0.f, 0.f, 0.f);
        #pragma unroll 4
        for (int j = 0; j < nn; j++) {
            float v = vp[j];
            float4 xv = b1[(ip[j] << lgc) + cc];
            a.x += v * xv.x; a.y += v * xv.y; a.z += v * xv.z; a.w += v * xv.w;
        }
        float4 x0v = b0[e];
        a.x = 2.f * a.x - x0v.x; a.y = 2.f * a.y - x0v.y;
        a.z = 2.f * a.z - x0v.z; a.w = 2.f * a.w - x0v.w;
        b0[e] = a;
        Z1[(size_t)row * cols4 + c0 + cc] = a;
    }
    __syncthreads();
    // pass3: x3 = 2 L x2 - x1
    for (int e = tid; e < 3072; e += 256) {
        int row = e >> lgc, cc = e & (colt4 - 1);
        const int* ip = idx + row * MAXNNZ;
        const float* vp = val + row * MAXNNZ;
        int nn = nnz[row];
        float4 a = make_float4(0.f, 0.f, 0.f, 0.f);
        #pragma unroll 4
        for (int j = 0; j < nn; j++) {
            float v = vp[j];
            float4 xv = b0[(ip[j] << lgc) + cc];
            a.x += v * xv.x; a.y += v * xv.y; a.z += v * xv.z; a.w += v * xv.w;
        }
        float4 x1v = b1[e];
        a.x = 2.f * a.x - x1v.x; a.y = 2.f * a.y - x1v.y;
        a.z = 2.f * a.z - x1v.z; a.w = 2.f * a.w - x1v.w;
        Z2[(size_t)row * cols4 + c0 + cc] = a;
    }
}

// Decoder Horner: z1 = L p0 + p1; z2 = L z1 + p2; out = L z2 + p3 [+ BN stats].
// P slabs at P + j*ps4 (float4 units). Intermediates stay in smem.
__global__ __launch_bounds__(256) void horner3_dec_k(
        const int* __restrict__ idx, const float* __restrict__ val,
        const int* __restrict__ nnz, int cols4, int lgc,
        const float4* __restrict__ P, size_t ps4,
        float4* __restrict__ out,
        float* __restrict__ sums, float* __restrict__ sqs, int fomask) {
    extern __shared__ float4 sm[];
    float4* b0 = sm;
    float4* b1 = sm + 3072;
    __shared__ float csum[256], csq[256];
    int colt4 = 1 << lgc;
    int c0 = blockIdx.x << lgc;
    int tid = threadIdx.x;
    if (sums) { csum[tid] = 0.f; csq[tid] = 0.f; }

    for (int e = tid; e < 3072; e += 256) {
        int row = e >> lgc, cc = e & (colt4 - 1);
        b0[e] = P[(size_t)row * cols4 + c0 + cc];
    }
    __syncthreads();
    // pass1: z1 = L p0 + p1
    for (int e = tid; e < 3072; e += 256) {
        int row = e >> lgc, cc = e & (colt4 - 1);
        const int* ip = idx + row * MAXNNZ;
        const float* vp = val + row * MAXNNZ;
        int nn = nnz[row];
        float4 a = P[ps4 + (size_t)row * cols4 + c0 + cc];
        #pragma unroll 4
        for (int j = 0; j < nn; j++) {
            float v = vp[j];
            float4 xv = b0[(ip[j] << lgc) + cc];
            a.x += v * xv.x; a.y += v * xv.y; a.z += v * xv.z; a.w += v * xv.w;
        }
        b1[e] = a;
    }
    __syncthreads();
    // pass2: z2 = L z1 + p2
    for (int e = tid; e < 3072; e += 256) {
        int row = e >> lgc, cc = e & (colt4 - 1);
        const int* ip = idx + row * MAXNNZ;
        const float* vp = val + row * MAXNNZ;
        int nn = nnz[row];
        float4 a = P[2 * ps4 + (size_t)row * cols4 + c0 + cc];
        #pragma unroll 4
        for (int j = 0; j < nn; j++) {
            float v = vp[j];
            float4 xv = b1[(ip[j] << lgc) + cc];
            a.x += v * xv.x; a.y += v * xv.y; a.z += v * xv.z; a.w += v * xv.w;
        }
        b0[e] = a;
    }
    __syncthreads();
    // pass3: out = L z2 + p3 (+ stats)
    float lp = 0.f, lq = 0.f;  // unused if !sums (kept simple: per-element atomics)
    (void)lp; (void)lq;
    for (int e = tid; e < 3072; e += 256) {
        int row = e >> lgc, cc = e & (colt4 - 1);
        const int* ip = idx + row * MAXNNZ;
        const float* vp = val + row * MAXNNZ;
        int nn = nnz[row];
        float4 a = P[3 * ps4 + (size_t)row * cols4 + c0 + cc];
        #pragma unroll 4
        for (int j = 0; j < nn; j++) {
            float v = vp[j];
            float4 xv = b0[(ip[j] << lgc) + cc];
            a.x += v * xv.x; a.y += v * xv.y; a.z += v * xv.z; a.w += v * xv.w;
        }
        out[(size_t)row * cols4 + c0 + cc] = a;
        if (sums) {
            int cb = (c0 + cc) << 2;
            atomicAdd(&csum[cb & fomask], a.x);       atomicAdd(&csq[cb & fomask], a.x * a.x);
            atomicAdd(&csum[(cb + 1) & fomask], a.y); atomicAdd(&csq[(cb + 1) & fomask], a.y * a.y);
            atomicAdd(&csum[(cb + 2) & fomask], a.z); atomicAdd(&csq[(cb + 2) & fomask], a.z * a.z);
            atomicAdd(&csum[(cb + 3) & fomask], a.w); atomicAdd(&csq[(cb + 3) & fomask], a.w * a.w);
        }
    }
    if (sums) {
        __syncthreads();
        if (tid <= fomask) {
            atomicAdd(&sums[tid], csum[tid]);
            atomicAdd(&sqs[tid], csq[tid]);
        }
    }
}

// ---------------- bf16x3 tensor-core GEMM, double-buffered ----------------

__device__ __forceinline__ void bsplit(float x, __nv_bfloat16& h, __nv_bfloat16& l) {
    h = __float2bfloat16_rn(x);
    l = __float2bfloat16_rn(x - __bfloat162float(h));
}

#define MMA_BF16(d, a, b) \
    asm volatile("mma.sync.aligned.m16n8k16.row.col.f32.bf16.bf16.f32 " \
        "{%0,%1,%2,%3},{%4,%5,%6,%7},{%8,%9},{%0,%1,%2,%3};" \
        : "+f"(d[0]), "+f"(d[1]), "+f"(d[2]), "+f"(d[3]) \
        : "r"(a[0]), "r"(a[1]), "r"(a[2]), "r"(a[3]), "r"(b[0]), "r"(b[1]))

template<int BN, int WM, int WN, bool CONCAT>
__global__ __launch_bounds__(256) void gemm_tc_k(
        const float* __restrict__ A0, const float* __restrict__ Zb,
        const float* __restrict__ W, float* __restrict__ C,
        int F, int lgF, int No,
        float* __restrict__ sums, float* __restrict__ sqs,
        int split_fo, size_t psz,
        int Fu, int Fs,
        const float* __restrict__ bng, const float* __restrict__ bnb,
        const float* __restrict__ bnsums, const float* __restrict__ bnsqs,
        float bninvM, int Ktot) {
    constexpr int SA = 18;
    constexpr int MT = WM / 16;
    constexpr int NT = WN / 8;
    constexpr int WNC = BN / WN;
    constexpr int WT4 = 16 * BN / 4;
    constexpr int WREG = (WT4 + 255) / 256;
    __shared__ alignas(16) __nv_bfloat16 Ah[2][128 * SA];
    __shared__ alignas(16) __nv_bfloat16 Al[2][128 * SA];
    __shared__ alignas(16) __nv_bfloat16 Wh[2][BN * SA];
    __shared__ alignas(16) __nv_bfloat16 Wl[2][BN * SA];
    __shared__ float csum[BN], csq[BN];
    __shared__ float scs[256], shs[256];

    int tid = threadIdx.x;
    int wid = tid >> 5, lane = tid & 31;
    int g = lane >> 2, t = lane & 3;
    int wm_id = wid / WNC, wn_id = wid % WNC;
    int m_base = wm_id * WM, n_base = wn_id * WN;
    int m0 = blockIdx.x * 128, n0 = blockIdx.y * BN;

    if (CONCAT && tid < Fu) {
        float mu = bnsums[tid] * bninvM;
        float var = bnsqs[tid] * bninvM - mu * mu;
        float sc = rsqrtf(var + 1e-5f) * bng[tid];
        scs[tid] = sc; shs[tid] = bnb[tid] - mu * sc;
    }

    float acc[MT][NT][4];
    #pragma unroll
    for (int i = 0; i < MT; i++)
        #pragma unroll
        for (int j = 0; j < NT; j++)
            #pragma unroll
            for (int q = 0; q < 4; q++) acc[i][j][q] = 0.f;

    auto ldA = [&](int kt, float4* aR) {
        #pragma unroll
        for (int i = 0; i < 2; i++) {
            int e = tid + i * 256;
            int mm = e >> 2, kk4 = (e & 3) * 4;
            int gf = kt + kk4;
            const float* p;
            if (CONCAT) {
                int m = m0 + mm; int n = m >> 8; int bg = m & 255;
                if (gf < Fu) p = &A0[((size_t)((n >> 2) << 8) + bg) * Fu + gf];
                else         p = &Zb[((size_t)(n << 8) + bg) * Fs + (gf - Fu)];
            } else {
                int seg = gf >> lgF;
                int fk = gf - (seg << lgF);
                const float* Ap = (seg == 0) ? A0 : (Zb + (size_t)(seg - 1) * SLICE);
                p = &Ap[(size_t)(m0 + mm) * F + fk];
            }
            aR[i] = __ldg((const float4*)p);
        }
    };
    auto ldW = [&](int kt, float4* wR) {
        #pragma unroll
        for (int i = 0; i < WREG; i++) {
            int e = tid + i * 256;
            if (e < WT4) {
                int kk = e / (BN / 4), nnq = (e % (BN / 4)) * 4;
                wR[i] = __ldg((const float4*)&W[(size_t)(kt + kk) * No + n0 + nnq]);
            }
        }
    };
    auto stA = [&](int kt, const float4* aR, int buf) {
        #pragma unroll
        for (int i = 0; i < 2; i++) {
            int e = tid + i * 256;
            int mm = e >> 2, kk4 = (e & 3) * 4;
            float4 v = aR[i];
            if (CONCAT) {
                int gf = kt + kk4;
                if (gf < Fu) {
                    v.x = fmaxf(v.x * scs[gf]     + shs[gf],     0.f);
                    v.y = fmaxf(v.y * scs[gf + 1] + shs[gf + 1], 0.f);
                    v.z = fmaxf(v.z * scs[gf + 2] + shs[gf + 2], 0.f);
                    v.w = fmaxf(v.w * scs[gf + 3] + shs[gf + 3], 0.f);
                }
            }
            int o = mm * SA + kk4;
            __nv_bfloat16 h, l;
            bsplit(v.x, h, l); Ah[buf][o]     = h; Al[buf][o]     = l;
            bsplit(v.y, h, l); Ah[buf][o + 1] = h; Al[buf][o + 1] = l;
            bsplit(v.z, h, l); Ah[buf][o + 2] = h; Al[buf][o + 2] = l;
            bsplit(v.w, h, l); Ah[buf][o + 3] = h; Al[buf][o + 3] = l;
        }
    };
    auto stW = [&](const float4* wR, int buf) {
        #pragma unroll
        for (int i = 0; i < WREG; i++) {
            int e = tid + i * 256;
            if (e < WT4) {
                int kk = e / (BN / 4), nnq = (e % (BN / 4)) * 4;
                float4 v = wR[i];
                __nv_bfloat16 h, l;
                bsplit(v.x, h, l); Wh[buf][(nnq + 0) * SA + kk] = h; Wl[buf][(nnq + 0) * SA + kk] = l;
                bsplit(v.y, h, l); Wh[buf][(nnq + 1) * SA + kk] = h; Wl[buf][(nnq + 1) * SA + kk] = l;
                bsplit(v.z, h, l); Wh[buf][(nnq + 2) * SA + kk] = h; Wl[buf][(nnq + 2) * SA + kk] = l;
                bsplit(v.w, h, l); Wh[buf][(nnq + 3) * SA + kk] = h; Wl[buf][(nnq + 3) * SA + kk] = l;
            }
        }
    };

    float4 aR[2], wR[WREG], aR2[2], wR2[WREG];
    ldA(0, aR); ldW(0, wR);
    __syncthreads();
    stA(0, aR, 0); stW(wR, 0);
    __syncthreads();
    int buf = 0;
    for (int kt = 0; kt < Ktot; kt += 16) {
        bool nb = (kt + 16) < Ktot;
        if (nb) { ldA(kt + 16, aR2); ldW(kt + 16, wR2); }

        uint32_t af[MT][4], bhf[NT][2], blf[NT][2];
        #pragma unroll
        for (int mt = 0; mt < MT; mt++) {
            int rb = (m_base + mt * 16 + g) * SA;
            af[mt][0] = *(const uint32_t*)&Ah[buf][rb + 2 * t];
            af[mt][1] = *(const uint32_t*)&Ah[buf][rb + 8 * SA + 2 * t];
            af[mt][2] = *(const uint32_t*)&Ah[buf][rb + 2 * t + 8];
            af[mt][3] = *(const uint32_t*)&Ah[buf][rb + 8 * SA + 2 * t + 8];
        }
        #pragma unroll
        for (int nt = 0; nt < NT; nt++) {
            int nb2 = (n_base + nt * 8 + g) * SA;
            bhf[nt][0] = *(const uint32_t*)&Wh[buf][nb2 + 2 * t];
            bhf[nt][1] = *(const uint32_t*)&Wh[buf][nb2 + 2 * t + 8];
            blf[nt][0] = *(const uint32_t*)&Wl[buf][nb2 + 2 * t];
            blf[nt][1] = *(const uint32_t*)&Wl[buf][nb2 + 2 * t + 8];
        }
        #pragma unroll
        for (int mt = 0; mt < MT; mt++)
            #pragma unroll
            for (int nt = 0; nt < NT; nt++)
                MMA_BF16(acc[mt][nt], af[mt], bhf[nt]);
        #pragma unroll
        for (int mt = 0; mt < MT; mt++)
            #pragma unroll
            for (int nt = 0; nt < NT; nt++)
                MMA_BF16(acc[mt][nt], af[mt], blf[nt]);
        #pragma unroll
        for (int mt = 0; mt < MT; mt++) {
            int rb = (m_base + mt * 16 + g) * SA;
            af[mt][0] = *(const uint32_t*)&Al[buf][rb + 2 * t];
            af[mt][1] = *(const uint32_t*)&Al[buf][rb + 8 * SA + 2 * t];
            af[mt][2] = *(const uint32_t*)&Al[buf][rb + 2 * t + 8];
            af[mt][3] = *(const uint32_t*)&Al[buf][rb + 8 * SA + 2 * t + 8];
        }
        #pragma unroll
        for (int mt = 0; mt < MT; mt++)
            #pragma unroll
            for (int nt = 0; nt < NT; nt++)
                MMA_BF16(acc[mt][nt], af[mt], bhf[nt]);

        if (nb) { stA(kt + 16, aR2, buf ^ 1); stW(wR2, buf ^ 1); }
        __syncthreads();
        buf ^= 1;
    }

    if (tid < BN) { csum[tid] = 0.f; csq[tid] = 0.f; }
    __syncthreads();
    float cp[NT][2], cq[NT][2];
    #pragma unroll
    for (int nt = 0; nt < NT; nt++) {
        cp[nt][0] = cp[nt][1] = 0.f; cq[nt][0] = cq[nt][1] = 0.f;
    }
    #pragma unroll
    for (int mt = 0; mt < MT; mt++) {
        size_t r0 = (size_t)(m0 + m_base + mt * 16 + g);
        size_t r1 = r0 + 8;
        #pragma unroll
        for (int nt = 0; nt < NT; nt++) {
            int col0 = n0 + n_base + nt * 8 + 2 * t;
            size_t o0, o1;
            if (split_fo) {
                int j = col0 / split_fo;
                int off = col0 - j * split_fo;
                o0 = (size_t)j * psz + r0 * split_fo + off;
                o1 = (size_t)j * psz + r1 * split_fo + off;
            } else {
                o0 = r0 * No + col0;
                o1 = r1 * No + col0;
            }
            float v0 = acc[mt][nt][0], v1 = acc[mt][nt][1];
            float v2 = acc[mt][nt][2], v3 = acc[mt][nt][3];
            C[o0] = v0; C[o0 + 1] = v1; C[o1] = v2; C[o1 + 1] = v3;
            cp[nt][0] += v0 + v2; cp[nt][1] += v1 + v3;
            cq[nt][0] += v0 * v0 + v2 * v2; cq[nt][1] += v1 * v1 + v3 * v3;
        }
    }
    if (sums) {
        #pragma unroll
        for (int nt = 0; nt < NT; nt++) {
            int cb = n_base + nt * 8 + 2 * t;
            atomicAdd(&csum[cb], cp[nt][0]);     atomicAdd(&csq[cb], cq[nt][0]);
            atomicAdd(&csum[cb + 1], cp[nt][1]); atomicAdd(&csq[cb + 1], cq[nt][1]);
        }
        __syncthreads();
        if (tid < BN) {
            atomicAdd(&sums[n0 + tid], csum[tid]);
            atomicAdd(&sqs[n0 + tid], csq[tid]);
        }
    }
}

// BN+ReLU in place (e3a only)
__global__ void bn_apply_k(float* __restrict__ Y, const float* __restrict__ g,
                           const float* __restrict__ b, size_t total, int mask,
                           float invM, const float* __restrict__ sums,
                           const float* __restrict__ sqs) {
    size_t e = (size_t)blockIdx.x * blockDim.x + threadIdx.x;
    if (e >= total) return;
    int f = (int)(e & (size_t)mask);
    float mu = sums[f] * invM;
    float var = sqs[f] * invM - mu * mu;
    float v = (Y[e] - mu) * rsqrtf(var + 1e-5f) * g[f] + b[f];
    Y[e] = v > 0.f ? v : 0.f;
}

// Fused BN+ReLU (in place on Y) + 4:1 max pool into P. Y: (4*Nout, B, F)
__global__ void bn_pool_k(float* __restrict__ Y, float* __restrict__ P,
                          const float* __restrict__ g, const float* __restrict__ b,
                          int Nout, int F, float invM,
                          const float* __restrict__ sums, const float* __restrict__ sqs) {
    int t = blockIdx.x * blockDim.x + threadIdx.x;
    int total = Nout * BG * F;
    if (t >= total) return;
    int f = t % F; int rb = t / F; int bb = rb % BG; int n2 = rb / BG;
    float mu = sums[f] * invM;
    float var = sqs[f] * invM - mu * mu;
    float sc = rsqrtf(var + 1e-5f) * g[f];
    float sh = b[f] - mu * sc;
    size_t base = ((size_t)(n2 * 4) * BG + bb) * F + f;
    size_t stride = (size_t)BG * F;
    float m = -1e30f;
    #pragma unroll
    for (int i = 0; i < 4; i++) {
        float v = Y[base + i * stride] * sc + sh;
        v = v > 0.f ? v : 0.f;
        Y[base + i * stride] = v;
        m = fmaxf(m, v);
    }
    P[t] = m;
}

// Out layer projections: BN+ReLU(X row, d3 stats) then 4 dots with Horner weights.
__global__ void proj4_k(const float* __restrict__ X, const float* __restrict__ wc,
                        float* __restrict__ P, int M, size_t psz,
                        const float* __restrict__ g, const float* __restrict__ b,
                        float invM, const float* __restrict__ sums,
                        const float* __restrict__ sqs) {
    int gw = (int)((blockIdx.x * blockDim.x + threadIdx.x) >> 5);
    int lane = threadIdx.x & 31;
    if (gw >= M) return;
    float x = X[(size_t)gw * 32 + lane];
    float mu = sums[lane] * invM;
    float var = sqs[lane] * invM - mu * mu;
    float xb = (x - mu) * rsqrtf(var + 1e-5f) * g[lane] + b[lane];
    xb = xb > 0.f ? xb : 0.f;
    float a0 = xb * wc[lane * 4 + 0];
    float a1 = xb * wc[lane * 4 + 1];
    float a2 = xb * wc[lane * 4 + 2];
    float a3 = xb * wc[lane * 4 + 3];
    #pragma unroll
    for (int o = 16; o; o >>= 1) {
        a0 += __shfl_down_sync(0xffffffffu, a0, o);
        a1 += __shfl_down_sync(0xffffffffu, a1, o);
        a2 += __shfl_down_sync(0xffffffffu, a2, o);
        a3 += __shfl_down_sync(0xffffffffu, a3, o);
    }
    if (lane == 0) {
        P[gw] = a0; P[psz + gw] = a1; P[2 * psz + gw] = a2; P[3 * psz + gw] = a3;
    }
}

// Y layout row = n*256 + bg  ->  out (4,1,8,8,768)
__global__ void reshape_out_k(const float* __restrict__ Y, float* __restrict__ out) {
    int t = blockIdx.x * blockDim.x + threadIdx.x;
    int n = t % 768;
    int r = t / 768;
    int hw = r & 63;
    int b0 = r >> 6;
    out[t] = Y[(size_t)n * BG + (size_t)b0 * 64 + hw];
}

// ---------------- host side ----------------

static int ilog2i(int v) { int l = 0; while ((1 << l) < v) l++; return l; }

extern "C" void kernel_launch(void* const* d_in, const int* in_sizes, int n_in,
                              void* d_out, int out_size) {
    const float* x = (const float*)d_in[0];

    float *A_, *B_, *Z_, *S3, *S2, *S1, *Wc, *sum_, *sq_, *cval;
    int *cidx, *cnnz;
    cudaGetSymbolAddress((void**)&A_,  g_A);
    cudaGetSymbolAddress((void**)&B_,  g_B);
    cudaGetSymbolAddress((void**)&Z_,  g_Z);
    cudaGetSymbolAddress((void**)&S3,  g_S3);
    cudaGetSymbolAddress((void**)&S2,  g_S2);
    cudaGetSymbolAddress((void**)&S1,  g_S1);
    cudaGetSymbolAddress((void**)&Wc,  g_Wc);
    cudaGetSymbolAddress((void**)&sum_, g_sum);
    cudaGetSymbolAddress((void**)&sq_,  g_sq);
    cudaGetSymbolAddress((void**)&cidx, g_cidx);
    cudaGetSymbolAddress((void**)&cval, g_cval);
    cudaGetSymbolAddress((void**)&cnnz, g_cnnz);

    static bool attr_done = false;
    if (!attr_done) {
        cudaFuncSetAttribute(cheb3_enc_k, cudaFuncAttributeMaxDynamicSharedMemorySize, 98304);
        cudaFuncSetAttribute(horner3_dec_k, cudaFuncAttributeMaxDynamicSharedMemorySize, 98304);
        attr_done = true;
    }

    const float* w_e3a = (const float*)d_in[5];
    const float* g_e3a_ = (const float*)d_in[6];  const float* b_e3a_ = (const float*)d_in[7];
    const float* w_e3b = (const float*)d_in[8];
    const float* g_e3b_ = (const float*)d_in[9];  const float* b_e3b_ = (const float*)d_in[10];
    const float* w_e2 = (const float*)d_in[11];
    const float* g_e2_ = (const float*)d_in[12];  const float* b_e2_ = (const float*)d_in[13];
    const float* w_e1 = (const float*)d_in[14];
    const float* g_e1_ = (const float*)d_in[15];  const float* b_e1_ = (const float*)d_in[16];
    const float* w_e0 = (const float*)d_in[17];
    const float* g_e0_ = (const float*)d_in[18];  const float* b_e0_ = (const float*)d_in[19];
    const float* w_d1 = (const float*)d_in[20];
    const float* g_d1_ = (const float*)d_in[21];  const float* b_d1_ = (const float*)d_in[22];
    const float* w_d2 = (const float*)d_in[23];
    const float* g_d2_ = (const float*)d_in[24];  const float* b_d2_ = (const float*)d_in[25];
    const float* w_d3 = (const float*)d_in[26];
    const float* g_d3_ = (const float*)d_in[27];  const float* b_d3_ = (const float*)d_in[28];
    const float* w_out = (const float*)d_in[29];

    zero_all_k<<<8, 256>>>(sum_, sq_);
    build_all_k<<<8, 128>>>((const float*)d_in[1], (const float*)d_in[2],
                            (const float*)d_in[3], (const float*)d_in[4],
                            cidx, cval, cnnz);
    wcomb_all_k<<<(86048 + 255) / 256, 256>>>(w_d1, w_d2, w_d3, w_out, Wc);
    transpose_in_k<<<6144, 256>>>(x, A_);

    // fused Chebyshev x1,x2,x3 (encoder)
    auto cheb3 = [&](int lvl, int N, int F, const float* in) {
        int cols4 = BG * F / 4;
        int colt4 = 3072 / N;
        int lgc = ilog2i(colt4);
        int blocks = cols4 / colt4;
        cheb3_enc_k<<<blocks, 256, 98304>>>(
            cidx + lvl * 768 * MAXNNZ, cval + lvl * 768 * MAXNNZ, cnnz + lvl * 768,
            cols4, lgc, (const float4*)in, Z_);
    };

    // fused Horner chain (decoder / out layer)
    auto hdec = [&](int lvl, int N, int Fo, float* outp, float* su, float* sqp) {
        int cols4 = BG * Fo / 4;
        int colt4 = 3072 / N;
        int lgc = ilog2i(colt4);
        int blocks = cols4 / colt4;
        size_t ps4 = (size_t)N * BG * Fo / 4;
        horner3_dec_k<<<blocks, 256, 98304>>>(
            cidx + lvl * 768 * MAXNNZ, cval + lvl * 768 * MAXNNZ, cnnz + lvl * 768,
            cols4, lgc, (const float4*)Z_, ps4, (float4*)outp, su, sqp, Fo - 1);
    };

    // plain (encoder) GEMM: 4 segments, Ktot = 4F
    auto run_tc = [&](const float* A0, const float* Zbp, const float* W, float* C,
                      int M, int F, int lgF, int No, float* su, float* sq) {
        int Ktot = 4 * F;
        if (No >= 128) {
            dim3 g(M / 128, No / 128);
            gemm_tc_k<128, 64, 32, false><<<g, 256>>>(A0, Zbp, W, C, F, lgF, No, su, sq,
                0, 0, 0, 0, nullptr, nullptr, nullptr, nullptr, 0.f, Ktot);
        } else if (No == 64) {
            gemm_tc_k<64, 32, 32, false><<<M / 128, 256>>>(A0, Zbp, W, C, F, lgF, No, su, sq,
                0, 0, 0, 0, nullptr, nullptr, nullptr, nullptr, 0.f, Ktot);
        } else {
            gemm_tc_k<32, 32, 16, false><<<M / 128, 256>>>(A0, Zbp, W, C, F, lgF, No, su, sq,
                0, 0, 0, 0, nullptr, nullptr, nullptr, nullptr, 0.f, Ktot);
        }
    };

    // -------- encoder --------
    cheb3(0, 768, 8, A_);
    run_tc(A_, Z_, w_e3a, B_, 196608, 8, 3, 32, sum_ + 0, sq_ + 0);
    bn_apply_k<<<(196608 * 32 + 255) / 256, 256>>>(B_, g_e3a_, b_e3a_,
        (size_t)196608 * 32, 31, 1.0f / 196608.f, sum_ + 0, sq_ + 0);

    cheb3(0, 768, 32, B_);
    run_tc(B_, Z_, w_e3b, S3, 196608, 32, 5, 64, sum_ + 256, sq_ + 256);
    bn_pool_k<<<(192 * BG * 64 + 255) / 256, 256>>>(S3, A_, g_e3b_, b_e3b_, 192, 64,
        1.0f / 196608.f, sum_ + 256, sq_ + 256);

    cheb3(1, 192, 64, A_);
    run_tc(A_, Z_, w_e2, S2, 49152, 64, 6, 128, sum_ + 512, sq_ + 512);
    bn_pool_k<<<(48 * BG * 128 + 255) / 256, 256>>>(S2, A_, g_e2_, b_e2_, 48, 128,
        1.0f / 49152.f, sum_ + 512, sq_ + 512);

    cheb3(2, 48, 128, A_);
    run_tc(A_, Z_, w_e1, S1, 12288, 128, 7, 256, sum_ + 768, sq_ + 768);
    bn_pool_k<<<(12 * BG * 256 + 255) / 256, 256>>>(S1, A_, g_e1_, b_e1_, 12, 256,
        1.0f / 12288.f, sum_ + 768, sq_ + 768);

    cheb3(3, 12, 256, A_);
    run_tc(A_, Z_, w_e0, B_, 3072, 256, 8, 256, sum_ + 1024, sq_ + 1024);

    // -------- decoder: concat GEMM (fused unpool+BN) + fused Horner chain --------
    auto deco_gemm = [&](int N, int Fu, int Fs, int Fo, const float* Wcp,
                         const float* H, const float* S,
                         const float* bg_, const float* bb_,
                         const float* bsum, const float* bsq, float binv) {
        int M = N * BG;
        size_t PS = (size_t)M * Fo;
        int F = Fu + Fs;
        int No = 4 * Fo;
        dim3 g(M / 128, No / 128);
        gemm_tc_k<128, 64, 32, true><<<g, 256>>>(H, S, Wcp, Z_, F, 0, No,
            nullptr, nullptr, Fo, PS, Fu, Fs, bg_, bb_, bsum, bsq, binv, F);
    };

    // d1
    deco_gemm(48, 256, 256, 128, Wc + W1OFF, B_, S1,
              g_e0_, b_e0_, sum_ + 1024, sq_ + 1024, 1.0f / 3072.f);
    hdec(2, 48, 128, A_, sum_ + 1280, sq_ + 1280);
    // d2
    deco_gemm(192, 128, 128, 64, Wc + W2OFF, A_, S2,
              g_d1_, b_d1_, sum_ + 1280, sq_ + 1280, 1.0f / 12288.f);
    hdec(1, 192, 64, B_, sum_ + 1536, sq_ + 1536);
    // d3
    deco_gemm(768, 64, 64, 32, Wc + W3OFF, B_, S3,
              g_d2_, b_d2_, sum_ + 1536, sq_ + 1536, 1.0f / 49152.f);
    hdec(0, 768, 32, A_, sum_ + 1792, sq_ + 1792);

    // -------- out layer (32 -> 1), BN(d3) fused into projection --------
    {
        int M = 196608;
        proj4_k<<<(M * 32 + 255) / 256, 256>>>(A_, Wc + W4OFF, Z_, M, (size_t)M,
            g_d3_, b_d3_, 1.0f / 196608.f, sum_ + 1792, sq_ + 1792);
        hdec(0, 768, 1, B_, nullptr, nullptr);
    }
    reshape_out_k<<<196608 / 256, 256>>>(B_, (float*)d_out);
}

// round 11
// speedup vs baseline: 1.2434x; 1.2434x over previous
#include <cuda_runtime.h>
#include <cuda_bf16.h>
#include <cstdint>
#include <cstddef>

#define MAXNNZ 40
#define BG 256
#define SLICE 25165824UL   // 768*256*128 floats (largest N*B*F slab)

// Wc offsets (floats): d1 512x512, d2 256x256, d3 128x128, out 32x4
#define W1OFF 0
#define W2OFF 262144
#define W3OFF 327680
#define W4OFF 344064

// ---------------- static scratch (no allocation allowed) ----------------
__device__ float g_A[SLICE];                 // ping buffer (N,B,F)
__device__ float g_B[SLICE];                 // pong buffer
__device__ float g_Z[3*SLICE];               // Chebyshev / Horner temporaries
__device__ float g_S3[768*256*64];           // skip s3
__device__ float g_S2[192*256*128];          // skip s2
__device__ float g_S1[48*256*256];           // skip s1
__device__ float g_Wc[360448];               // combined Horner weights (all layers)
__device__ int   g_cidx[4*768*MAXNNZ];       // ELL col indices per level
__device__ float g_cval[4*768*MAXNNZ];       // ELL values
__device__ int   g_cnnz[4*768];              // per-row nnz
__device__ float g_sum[8*256];               // BN channel sums (per layer)
__device__ float g_sq[8*256];                // BN channel sum-of-squares

// ---------------- small kernels ----------------

__global__ void zero_all_k(float* s, float* q) {
    int i = blockIdx.x * blockDim.x + threadIdx.x;
    s[i] = 0.f; q[i] = 0.f;
}

__global__ void build_all_k(const float* __restrict__ L3, const float* __restrict__ L2,
                            const float* __restrict__ L1, const float* __restrict__ L0,
                            int* __restrict__ idx, float* __restrict__ val,
                            int* __restrict__ nnz) {
    int t = blockIdx.x * blockDim.x + threadIdx.x;
    if (t >= 1020) return;
    int lvl, n, N;
    const float* L;
    if (t < 768)       { lvl = 0; n = t;        N = 768; L = L3; }
    else if (t < 960)  { lvl = 1; n = t - 768;  N = 192; L = L2; }
    else if (t < 1008) { lvl = 2; n = t - 960;  N = 48;  L = L1; }
    else               { lvl = 3; n = t - 1008; N = 12;  L = L0; }
    int base = (lvl * 768 + n) * MAXNNZ;
    int c = 0;
    for (int m = 0; m < N; m++) {
        float v = L[n * N + m];
        if (v != 0.0f && c < MAXNNZ) {
            idx[base + c] = m;
            val[base + c] = v;
            c++;
        }
    }
    nnz[lvl * 768 + n] = c;
}

// x (4,8,8,8,768) -> A layout (n, bg, c) with bg = b0*64 + hw
__global__ void transpose_in_k(const float* __restrict__ x, float* __restrict__ A) {
    int t = blockIdx.x * blockDim.x + threadIdx.x;
    int n = t % 768;
    int r = t / 768;
    int hw = r & 63; r >>= 6;
    int c = r & 7;  int b0 = r >> 3;
    A[((size_t)n * BG + (size_t)b0 * 64 + hw) * 8 + c] = x[t];
}

// All Horner weight combos in one launch.
__global__ void wcomb_all_k(const float* __restrict__ w1, const float* __restrict__ w2,
                            const float* __restrict__ w3, const float* __restrict__ w4,
                            float* __restrict__ wc) {
    int i = blockIdx.x * blockDim.x + threadIdx.x;
    const float* w; int Fo, off, r, FFo;
    if (i < 65536)      { w = w1; Fo = 128; off = W1OFF; r = i;         FFo = 65536; }
    else if (i < 81920) { w = w2; Fo = 64;  off = W2OFF; r = i - 65536; FFo = 16384; }
    else if (i < 86016) { w = w3; Fo = 32;  off = W3OFF; r = i - 81920; FFo = 4096;  }
    else if (i < 86048) { w = w4; Fo = 1;   off = W4OFF; r = i - 86016; FFo = 32;    }
    else return;
    int k = r / Fo, n = r - (r / Fo) * Fo;
    float w0 = w[r], wa = w[FFo + r], wb = w[2 * FFo + r], wd = w[3 * FFo + r];
    float* row = wc + off + (size_t)k * 4 * Fo + n;
    row[0]      = 4.f * wd;
    row[Fo]     = 2.f * wb;
    row[2 * Fo] = wa - 3.f * wd;
    row[3 * Fo] = w0 - wb;
}

// Z[row,:] = alpha * (L X)[row,:] + beta * S[row,:]  [+ fused BN stats]
// Two float4 columns per thread (col c and c + blockDim.x) for 2x MLP.
__global__ void spmm_k(const int* __restrict__ idx, const float* __restrict__ val,
                       const int* __restrict__ nnz, int cols4,
                       const float4* __restrict__ X, float4* __restrict__ Z,
                       float alpha, float beta, const float4* __restrict__ S,
                       float* __restrict__ sums, float* __restrict__ sqs, int chmask) {
    int row = blockIdx.y;
    int bd = blockDim.x;
    int c = blockIdx.x * (bd * 2) + threadIdx.x;   // col0 = c, col1 = c + bd
    __shared__ int   si[MAXNNZ];
    __shared__ float sv[MAXNNZ];
    __shared__ int   sn;
    __shared__ float csum[256], csq[256];
    int tid = threadIdx.x;
    for (int j = tid; j < MAXNNZ; j += bd) {
        si[j] = idx[row * MAXNNZ + j];
        sv[j] = val[row * MAXNNZ + j];
    }
    if (tid == 0) sn = nnz[row];
    if (sums) {
        for (int j = tid; j < 256; j += bd) { csum[j] = 0.f; csq[j] = 0.f; }
    }
    __syncthreads();
    float4 a0 = make_float4(0.f, 0.f, 0.f, 0.f);
    float4 a1 = make_float4(0.f, 0.f, 0.f, 0.f);
    int nn = sn;
    #pragma unroll 4
    for (int j = 0; j < nn; j++) {
        float v = sv[j];
        const float4* xr = X + (size_t)si[j] * cols4 + c;
        float4 x0 = __ldg(xr);
        float4 x1 = __ldg(xr + bd);
        a0.x += v * x0.x; a0.y += v * x0.y; a0.z += v * x0.z; a0.w += v * x0.w;
        a1.x += v * x1.x; a1.y += v * x1.y; a1.z += v * x1.z; a1.w += v * x1.w;
    }
    size_t o = (size_t)row * cols4 + c;
    float4 o0, o1;
    if (S) {
        float4 s0 = S[o], s1 = S[o + bd];
        o0 = make_float4(alpha * a0.x + beta * s0.x, alpha * a0.y + beta * s0.y,
                         alpha * a0.z + beta * s0.z, alpha * a0.w + beta * s0.w);
        o1 = make_float4(alpha * a1.x + beta * s1.x, alpha * a1.y + beta * s1.y,
                         alpha * a1.z + beta * s1.z, alpha * a1.w + beta * s1.w);
    } else {
        o0 = make_float4(alpha * a0.x, alpha * a0.y, alpha * a0.z, alpha * a0.w);
        o1 = make_float4(alpha * a1.x, alpha * a1.y, alpha * a1.z, alpha * a1.w);
    }
    Z[o] = o0;
    Z[o + bd] = o1;
    if (sums) {
        int cb0 = (c * 4) & chmask;
        int cb1 = ((c + bd) * 4) & chmask;
        atomicAdd(&csum[cb0],     o0.x); atomicAdd(&csq[cb0],     o0.x * o0.x);
        atomicAdd(&csum[cb0 + 1], o0.y); atomicAdd(&csq[cb0 + 1], o0.y * o0.y);
        atomicAdd(&csum[cb0 + 2], o0.z); atomicAdd(&csq[cb0 + 2], o0.z * o0.z);
        atomicAdd(&csum[cb0 + 3], o0.w); atomicAdd(&csq[cb0 + 3], o0.w * o0.w);
        atomicAdd(&csum[cb1],     o1.x); atomicAdd(&csq[cb1],     o1.x * o1.x);
        atomicAdd(&csum[cb1 + 1], o1.y); atomicAdd(&csq[cb1 + 1], o1.y * o1.y);
        atomicAdd(&csum[cb1 + 2], o1.z); atomicAdd(&csq[cb1 + 2], o1.z * o1.z);
        atomicAdd(&csum[cb1 + 3], o1.w); atomicAdd(&csq[cb1 + 3], o1.w * o1.w);
        __syncthreads();
        for (int j = tid; j <= chmask; j += bd) {
            atomicAdd(&sums[j], csum[j]);
            atomicAdd(&sqs[j], csq[j]);
        }
    }
}

// ---------------- bf16x3 tensor-core GEMM, double-buffered ----------------

__device__ __forceinline__ void bsplit(float x, __nv_bfloat16& h, __nv_bfloat16& l) {
    h = __float2bfloat16_rn(x);
    l = __float2bfloat16_rn(x - __bfloat162float(h));
}

#define MMA_BF16(d, a, b) \
    asm volatile("mma.sync.aligned.m16n8k16.row.col.f32.bf16.bf16.f32 " \
        "{%0,%1,%2,%3},{%4,%5,%6,%7},{%8,%9},{%0,%1,%2,%3};" \
        : "+f"(d[0]), "+f"(d[1]), "+f"(d[2]), "+f"(d[3]) \
        : "r"(a[0]), "r"(a[1]), "r"(a[2]), "r"(a[3]), "r"(b[0]), "r"(b[1]))

template<int BN, int WM, int WN, bool CONCAT>
__global__ __launch_bounds__(256) void gemm_tc_k(
        const float* __restrict__ A0, const float* __restrict__ Zb,
        const float* __restrict__ W, float* __restrict__ C,
        int F, int lgF, int No,
        float* __restrict__ sums, float* __restrict__ sqs,
        int split_fo, size_t psz,
        int Fu, int Fs,
        const float* __restrict__ bng, const float* __restrict__ bnb,
        const float* __restrict__ bnsums, const float* __restrict__ bnsqs,
        float bninvM, int Ktot) {
    constexpr int SA = 18;
    constexpr int MT = WM / 16;
    constexpr int NT = WN / 8;
    constexpr int WNC = BN / WN;
    constexpr int WT4 = 16 * BN / 4;
    constexpr int WREG = (WT4 + 255) / 256;
    __shared__ alignas(16) __nv_bfloat16 Ah[2][128 * SA];
    __shared__ alignas(16) __nv_bfloat16 Al[2][128 * SA];
    __shared__ alignas(16) __nv_bfloat16 Wh[2][BN * SA];
    __shared__ alignas(16) __nv_bfloat16 Wl[2][BN * SA];
    __shared__ float csum[BN], csq[BN];
    __shared__ float scs[256], shs[256];

    int tid = threadIdx.x;
    int wid = tid >> 5, lane = tid & 31;
    int g = lane >> 2, t = lane & 3;
    int wm_id = wid / WNC, wn_id = wid % WNC;
    int m_base = wm_id * WM, n_base = wn_id * WN;
    int m0 = blockIdx.x * 128, n0 = blockIdx.y * BN;

    if (CONCAT && tid < Fu) {
        float mu = bnsums[tid] * bninvM;
        float var = bnsqs[tid] * bninvM - mu * mu;
        float sc = rsqrtf(var + 1e-5f) * bng[tid];
        scs[tid] = sc; shs[tid] = bnb[tid] - mu * sc;
    }

    float acc[MT][NT][4];
    #pragma unroll
    for (int i = 0; i < MT; i++)
        #pragma unroll
        for (int j = 0; j < NT; j++)
            #pragma unroll
            for (int q = 0; q < 4; q++) acc[i][j][q] = 0.f;

    auto ldA = [&](int kt, float4* aR) {
        #pragma unroll
        for (int i = 0; i < 2; i++) {
            int e = tid + i * 256;
            int mm = e >> 2, kk4 = (e & 3) * 4;
            int gf = kt + kk4;
            const float* p;
            if (CONCAT) {
                int m = m0 + mm; int n = m >> 8; int bg = m & 255;
                if (gf < Fu) p = &A0[((size_t)((n >> 2) << 8) + bg) * Fu + gf];
                else         p = &Zb[((size_t)(n << 8) + bg) * Fs + (gf - Fu)];
            } else {
                int seg = gf >> lgF;
                int fk = gf - (seg << lgF);
                const float* Ap = (seg == 0) ? A0 : (Zb + (size_t)(seg - 1) * SLICE);
                p = &Ap[(size_t)(m0 + mm) * F + fk];
            }
            aR[i] = __ldg((const float4*)p);
        }
    };
    auto ldW = [&](int kt, float4* wR) {
        #pragma unroll
        for (int i = 0; i < WREG; i++) {
            int e = tid + i * 256;
            if (e < WT4) {
                int kk = e / (BN / 4), nnq = (e % (BN / 4)) * 4;
                wR[i] = __ldg((const float4*)&W[(size_t)(kt + kk) * No + n0 + nnq]);
            }
        }
    };
    auto stA = [&](int kt, const float4* aR, int buf) {
        #pragma unroll
        for (int i = 0; i < 2; i++) {
            int e = tid + i * 256;
            int mm = e >> 2, kk4 = (e & 3) * 4;
            float4 v = aR[i];
            if (CONCAT) {
                int gf = kt + kk4;
                if (gf < Fu) {
                    v.x = fmaxf(v.x * scs[gf]     + shs[gf],     0.f);
                    v.y = fmaxf(v.y * scs[gf + 1] + shs[gf + 1], 0.f);
                    v.z = fmaxf(v.z * scs[gf + 2] + shs[gf + 2], 0.f);
                    v.w = fmaxf(v.w * scs[gf + 3] + shs[gf + 3], 0.f);
                }
            }
            int o = mm * SA + kk4;
            __nv_bfloat16 h, l;
            bsplit(v.x, h, l); Ah[buf][o]     = h; Al[buf][o]     = l;
            bsplit(v.y, h, l); Ah[buf][o + 1] = h; Al[buf][o + 1] = l;
            bsplit(v.z, h, l); Ah[buf][o + 2] = h; Al[buf][o + 2] = l;
            bsplit(v.w, h, l); Ah[buf][o + 3] = h; Al[buf][o + 3] = l;
        }
    };
    auto stW = [&](const float4* wR, int buf) {
        #pragma unroll
        for (int i = 0; i < WREG; i++) {
            int e = tid + i * 256;
            if (e < WT4) {
                int kk = e / (BN / 4), nnq = (e % (BN / 4)) * 4;
                float4 v = wR[i];
                __nv_bfloat16 h, l;
                bsplit(v.x, h, l); Wh[buf][(nnq + 0) * SA + kk] = h; Wl[buf][(nnq + 0) * SA + kk] = l;
                bsplit(v.y, h, l); Wh[buf][(nnq + 1) * SA + kk] = h; Wl[buf][(nnq + 1) * SA + kk] = l;
                bsplit(v.z, h, l); Wh[buf][(nnq + 2) * SA + kk] = h; Wl[buf][(nnq + 2) * SA + kk] = l;
                bsplit(v.w, h, l); Wh[buf][(nnq + 3) * SA + kk] = h; Wl[buf][(nnq + 3) * SA + kk] = l;
            }
        }
    };

    float4 aR[2], wR[WREG], aR2[2], wR2[WREG];
    ldA(0, aR); ldW(0, wR);
    __syncthreads();
    stA(0, aR, 0); stW(wR, 0);
    __syncthreads();
    int buf = 0;
    for (int kt = 0; kt < Ktot; kt += 16) {
        bool nb = (kt + 16) < Ktot;
        if (nb) { ldA(kt + 16, aR2); ldW(kt + 16, wR2); }

        uint32_t af[MT][4], bhf[NT][2], blf[NT][2];
        #pragma unroll
        for (int mt = 0; mt < MT; mt++) {
            int rb = (m_base + mt * 16 + g) * SA;
            af[mt][0] = *(const uint32_t*)&Ah[buf][rb + 2 * t];
            af[mt][1] = *(const uint32_t*)&Ah[buf][rb + 8 * SA + 2 * t];
            af[mt][2] = *(const uint32_t*)&Ah[buf][rb + 2 * t + 8];
            af[mt][3] = *(const uint32_t*)&Ah[buf][rb + 8 * SA + 2 * t + 8];
        }
        #pragma unroll
        for (int nt = 0; nt < NT; nt++) {
            int nb2 = (n_base + nt * 8 + g) * SA;
            bhf[nt][0] = *(const uint32_t*)&Wh[buf][nb2 + 2 * t];
            bhf[nt][1] = *(const uint32_t*)&Wh[buf][nb2 + 2 * t + 8];
            blf[nt][0] = *(const uint32_t*)&Wl[buf][nb2 + 2 * t];
            blf[nt][1] = *(const uint32_t*)&Wl[buf][nb2 + 2 * t + 8];
        }
        #pragma unroll
        for (int mt = 0; mt < MT; mt++)
            #pragma unroll
            for (int nt = 0; nt < NT; nt++)
                MMA_BF16(acc[mt][nt], af[mt], bhf[nt]);
        #pragma unroll
        for (int mt = 0; mt < MT; mt++)
            #pragma unroll
            for (int nt = 0; nt < NT; nt++)
                MMA_BF16(acc[mt][nt], af[mt], blf[nt]);
        #pragma unroll
        for (int mt = 0; mt < MT; mt++) {
            int rb = (m_base + mt * 16 + g) * SA;
            af[mt][0] = *(const uint32_t*)&Al[buf][rb + 2 * t];
            af[mt][1] = *(const uint32_t*)&Al[buf][rb + 8 * SA + 2 * t];
            af[mt][2] = *(const uint32_t*)&Al[buf][rb + 2 * t + 8];
            af[mt][3] = *(const uint32_t*)&Al[buf][rb + 8 * SA + 2 * t + 8];
        }
        #pragma unroll
        for (int mt = 0; mt < MT; mt++)
            #pragma unroll
            for (int nt = 0; nt < NT; nt++)
                MMA_BF16(acc[mt][nt], af[mt], bhf[nt]);

        if (nb) { stA(kt + 16, aR2, buf ^ 1); stW(wR2, buf ^ 1); }
        __syncthreads();
        buf ^= 1;
    }

    if (tid < BN) { csum[tid] = 0.f; csq[tid] = 0.f; }
    __syncthreads();
    float cp[NT][2], cq[NT][2];
    #pragma unroll
    for (int nt = 0; nt < NT; nt++) {
        cp[nt][0] = cp[nt][1] = 0.f; cq[nt][0] = cq[nt][1] = 0.f;
    }
    #pragma unroll
    for (int mt = 0; mt < MT; mt++) {
        size_t r0 = (size_t)(m0 + m_base + mt * 16 + g);
        size_t r1 = r0 + 8;
        #pragma unroll
        for (int nt = 0; nt < NT; nt++) {
            int col0 = n0 + n_base + nt * 8 + 2 * t;
            size_t o0, o1;
            if (split_fo) {
                int j = col0 / split_fo;
                int off = col0 - j * split_fo;
                o0 = (size_t)j * psz + r0 * split_fo + off;
                o1 = (size_t)j * psz + r1 * split_fo + off;
            } else {
                o0 = r0 * No + col0;
                o1 = r1 * No + col0;
            }
            float v0 = acc[mt][nt][0], v1 = acc[mt][nt][1];
            float v2 = acc[mt][nt][2], v3 = acc[mt][nt][3];
            C[o0] = v0; C[o0 + 1] = v1; C[o1] = v2; C[o1 + 1] = v3;
            cp[nt][0] += v0 + v2; cp[nt][1] += v1 + v3;
            cq[nt][0] += v0 * v0 + v2 * v2; cq[nt][1] += v1 * v1 + v3 * v3;
        }
    }
    if (sums) {
        #pragma unroll
        for (int nt = 0; nt < NT; nt++) {
            int cb = n_base + nt * 8 + 2 * t;
            atomicAdd(&csum[cb], cp[nt][0]);     atomicAdd(&csq[cb], cq[nt][0]);
            atomicAdd(&csum[cb + 1], cp[nt][1]); atomicAdd(&csq[cb + 1], cq[nt][1]);
        }
        __syncthreads();
        if (tid < BN) {
            atomicAdd(&sums[n0 + tid], csum[tid]);
            atomicAdd(&sqs[n0 + tid], csq[tid]);
        }
    }
}

// BN+ReLU in place (e3a only)
__global__ void bn_apply_k(float* __restrict__ Y, const float* __restrict__ g,
                           const float* __restrict__ b, size_t total, int mask,
                           float invM, const float* __restrict__ sums,
                           const float* __restrict__ sqs) {
    size_t e = (size_t)blockIdx.x * blockDim.x + threadIdx.x;
    if (e >= total) return;
    int f = (int)(e & (size_t)mask);
    float mu = sums[f] * invM;
    float var = sqs[f] * invM - mu * mu;
    float v = (Y[e] - mu) * rsqrtf(var + 1e-5f) * g[f] + b[f];
    Y[e] = v > 0.f ? v : 0.f;
}

// Fused BN+ReLU (in place on Y) + 4:1 max pool into P. Y: (4*Nout, B, F)
__global__ void bn_pool_k(float* __restrict__ Y, float* __restrict__ P,
                          const float* __restrict__ g, const float* __restrict__ b,
                          int Nout, int F, float invM,
                          const float* __restrict__ sums, const float* __restrict__ sqs) {
    int t = blockIdx.x * blockDim.x + threadIdx.x;
    int total = Nout * BG * F;
    if (t >= total) return;
    int f = t % F; int rb = t / F; int bb = rb % BG; int n2 = rb / BG;
    float mu = sums[f] * invM;
    float var = sqs[f] * invM - mu * mu;
    float sc = rsqrtf(var + 1e-5f) * g[f];
    float sh = b[f] - mu * sc;
    size_t base = ((size_t)(n2 * 4) * BG + bb) * F + f;
    size_t stride = (size_t)BG * F;
    float m = -1e30f;
    #pragma unroll
    for (int i = 0; i < 4; i++) {
        float v = Y[base + i * stride] * sc + sh;
        v = v > 0.f ? v : 0.f;
        Y[base + i * stride] = v;
        m = fmaxf(m, v);
    }
    P[t] = m;
}

// Out layer projections: BN+ReLU(X row, d3 stats) then 4 dots with Horner weights.
__global__ void proj4_k(const float* __restrict__ X, const float* __restrict__ wc,
                        float* __restrict__ P, int M, size_t psz,
                        const float* __restrict__ g, const float* __restrict__ b,
                        float invM, const float* __restrict__ sums,
                        const float* __restrict__ sqs) {
    int gw = (int)((blockIdx.x * blockDim.x + threadIdx.x) >> 5);
    int lane = threadIdx.x & 31;
    if (gw >= M) return;
    float x = X[(size_t)gw * 32 + lane];
    float mu = sums[lane] * invM;
    float var = sqs[lane] * invM - mu * mu;
    float xb = (x - mu) * rsqrtf(var + 1e-5f) * g[lane] + b[lane];
    xb = xb > 0.f ? xb : 0.f;
    float a0 = xb * wc[lane * 4 + 0];
    float a1 = xb * wc[lane * 4 + 1];
    float a2 = xb * wc[lane * 4 + 2];
    float a3 = xb * wc[lane * 4 + 3];
    #pragma unroll
    for (int o = 16; o; o >>= 1) {
        a0 += __shfl_down_sync(0xffffffffu, a0, o);
        a1 += __shfl_down_sync(0xffffffffu, a1, o);
        a2 += __shfl_down_sync(0xffffffffu, a2, o);
        a3 += __shfl_down_sync(0xffffffffu, a3, o);
    }
    if (lane == 0) {
        P[gw] = a0; P[psz + gw] = a1; P[2 * psz + gw] = a2; P[3 * psz + gw] = a3;
    }
}

// Y layout row = n*256 + bg  ->  out (4,1,8,8,768)
__global__ void reshape_out_k(const float* __restrict__ Y, float* __restrict__ out) {
    int t = blockIdx.x * blockDim.x + threadIdx.x;
    int n = t % 768;
    int r = t / 768;
    int hw = r & 63;
    int b0 = r >> 6;
    out[t] = Y[(size_t)n * BG + (size_t)b0 * 64 + hw];
}

// ---------------- host side ----------------

extern "C" void kernel_launch(void* const* d_in, const int* in_sizes, int n_in,
                              void* d_out, int out_size) {
    const float* x = (const float*)d_in[0];

    float *A_, *B_, *Z_, *S3, *S2, *S1, *Wc, *sum_, *sq_, *cval;
    int *cidx, *cnnz;
    cudaGetSymbolAddress((void**)&A_,  g_A);
    cudaGetSymbolAddress((void**)&B_,  g_B);
    cudaGetSymbolAddress((void**)&Z_,  g_Z);
    cudaGetSymbolAddress((void**)&S3,  g_S3);
    cudaGetSymbolAddress((void**)&S2,  g_S2);
    cudaGetSymbolAddress((void**)&S1,  g_S1);
    cudaGetSymbolAddress((void**)&Wc,  g_Wc);
    cudaGetSymbolAddress((void**)&sum_, g_sum);
    cudaGetSymbolAddress((void**)&sq_,  g_sq);
    cudaGetSymbolAddress((void**)&cidx, g_cidx);
    cudaGetSymbolAddress((void**)&cval, g_cval);
    cudaGetSymbolAddress((void**)&cnnz, g_cnnz);

    const float* w_e3a = (const float*)d_in[5];
    const float* g_e3a_ = (const float*)d_in[6];  const float* b_e3a_ = (const float*)d_in[7];
    const float* w_e3b = (const float*)d_in[8];
    const float* g_e3b_ = (const float*)d_in[9];  const float* b_e3b_ = (const float*)d_in[10];
    const float* w_e2 = (const float*)d_in[11];
    const float* g_e2_ = (const float*)d_in[12];  const float* b_e2_ = (const float*)d_in[13];
    const float* w_e1 = (const float*)d_in[14];
    const float* g_e1_ = (const float*)d_in[15];  const float* b_e1_ = (const float*)d_in[16];
    const float* w_e0 = (const float*)d_in[17];
    const float* g_e0_ = (const float*)d_in[18];  const float* b_e0_ = (const float*)d_in[19];
    const float* w_d1 = (const float*)d_in[20];
    const float* g_d1_ = (const float*)d_in[21];  const float* b_d1_ = (const float*)d_in[22];
    const float* w_d2 = (const float*)d_in[23];
    const float* g_d2_ = (const float*)d_in[24];  const float* b_d2_ = (const float*)d_in[25];
    const float* w_d3 = (const float*)d_in[26];
    const float* g_d3_ = (const float*)d_in[27];  const float* b_d3_ = (const float*)d_in[28];
    const float* w_out = (const float*)d_in[29];

    zero_all_k<<<8, 256>>>(sum_, sq_);
    build_all_k<<<8, 128>>>((const float*)d_in[1], (const float*)d_in[2],
                            (const float*)d_in[3], (const float*)d_in[4],
                            cidx, cval, cnnz);
    wcomb_all_k<<<(86048 + 255) / 256, 256>>>(w_d1, w_d2, w_d3, w_out, Wc);
    transpose_in_k<<<6144, 256>>>(x, A_);

    auto spmm1 = [&](int lvl, int N, int F, const float* in, float* out,
                     float alpha, float beta, const float* S,
                     float* su, float* sq, int mask) {
        int cols4 = BG * F / 4;                 // >= 64, multiple of 64
        int thr = cols4 / 2 < 256 ? cols4 / 2 : 256;
        dim3 gs(cols4 / (thr * 2), N);
        spmm_k<<<gs, thr>>>(cidx + lvl * 768 * MAXNNZ, cval + lvl * 768 * MAXNNZ,
                            cnnz + lvl * 768, cols4, (const float4*)in, (float4*)out,
                            alpha, beta, (const float4*)S, su, sq, mask);
    };

    auto spmm3 = [&](int lvl, int N, int F, const float* in) {
        spmm1(lvl, N, F, in, Z_, 1.f, 0.f, nullptr, nullptr, nullptr, 0);
        spmm1(lvl, N, F, Z_, Z_ + SLICE, 2.f, -1.f, in, nullptr, nullptr, 0);
        spmm1(lvl, N, F, Z_ + SLICE, Z_ + 2 * SLICE, 2.f, -1.f, Z_, nullptr, nullptr, 0);
    };

    // plain (encoder) GEMM: 4 segments, Ktot = 4F
    auto run_tc = [&](const float* A0, const float* Zbp, const float* W, float* C,
                      int M, int F, int lgF, int No, float* su, float* sq) {
        int Ktot = 4 * F;
        if (No >= 128) {
            dim3 g(M / 128, No / 128);
            gemm_tc_k<128, 64, 32, false><<<g, 256>>>(A0, Zbp, W, C, F, lgF, No, su, sq,
                0, 0, 0, 0, nullptr, nullptr, nullptr, nullptr, 0.f, Ktot);
        } else if (No == 64) {
            gemm_tc_k<64, 32, 32, false><<<M / 128, 256>>>(A0, Zbp, W, C, F, lgF, No, su, sq,
                0, 0, 0, 0, nullptr, nullptr, nullptr, nullptr, 0.f, Ktot);
        } else {
            gemm_tc_k<32, 32, 16, false><<<M / 128, 256>>>(A0, Zbp, W, C, F, lgF, No, su, sq,
                0, 0, 0, 0, nullptr, nullptr, nullptr, nullptr, 0.f, Ktot);
        }
    };

    // -------- encoder --------
    spmm3(0, 768, 8, A_);
    run_tc(A_, Z_, w_e3a, B_, 196608, 8, 3, 32, sum_ + 0, sq_ + 0);
    bn_apply_k<<<(196608 * 32 + 255) / 256, 256>>>(B_, g_e3a_, b_e3a_,
        (size_t)196608 * 32, 31, 1.0f / 196608.f, sum_ + 0, sq_ + 0);

    spmm3(0, 768, 32, B_);
    run_tc(B_, Z_, w_e3b, S3, 196608, 32, 5, 64, sum_ + 256, sq_ + 256);
    bn_pool_k<<<(192 * BG * 64 + 255) / 256, 256>>>(S3, A_, g_e3b_, b_e3b_, 192, 64,
        1.0f / 196608.f, sum_ + 256, sq_ + 256);

    spmm3(1, 192, 64, A_);
    run_tc(A_, Z_, w_e2, S2, 49152, 64, 6, 128, sum_ + 512, sq_ + 512);
    bn_pool_k<<<(48 * BG * 128 + 255) / 256, 256>>>(S2, A_, g_e2_, b_e2_, 48, 128,
        1.0f / 49152.f, sum_ + 512, sq_ + 512);

    spmm3(2, 48, 128, A_);
    run_tc(A_, Z_, w_e1, S1, 12288, 128, 7, 256, sum_ + 768, sq_ + 768);
    bn_pool_k<<<(12 * BG * 256 + 255) / 256, 256>>>(S1, A_, g_e1_, b_e1_, 12, 256,
        1.0f / 12288.f, sum_ + 768, sq_ + 768);

    spmm3(3, 12, 256, A_);
    run_tc(A_, Z_, w_e0, B_, 3072, 256, 8, 256, sum_ + 1024, sq_ + 1024);

    // -------- decoder: concat GEMM (fused unpool+BN) + Horner spmm chain --------
    auto deco = [&](int lvl, int N, int Fu, int Fs, int Fo, const float* Wcp,
                    const float* H, const float* S,
                    const float* bg_, const float* bb_,
                    const float* bsum, const float* bsq, float binv,
                    float* out, float* su, float* sq) {
        int M = N * BG;
        size_t PS = (size_t)M * Fo;
        int F = Fu + Fs;
        int No = 4 * Fo;
        dim3 g(M / 128, No / 128);
        gemm_tc_k<128, 64, 32, true><<<g, 256>>>(H, S, Wcp, Z_, F, 0, No,
            nullptr, nullptr, Fo, PS, Fu, Fs, bg_, bb_, bsum, bsq, binv, F);
        spmm1(lvl, N, Fo, Z_,          Z_ + PS,     1.f, 1.f, Z_ + PS, nullptr, nullptr, 0);
        spmm1(lvl, N, Fo, Z_ + PS,     Z_ + 2 * PS, 1.f, 1.f, Z_ + 2 * PS, nullptr, nullptr, 0);
        spmm1(lvl, N, Fo, Z_ + 2 * PS, out,         1.f, 1.f, Z_ + 3 * PS, su, sq, Fo - 1);
    };

    // d1
    deco(2, 48, 256, 256, 128, Wc + W1OFF, B_, S1,
         g_e0_, b_e0_, sum_ + 1024, sq_ + 1024, 1.0f / 3072.f,
         A_, sum_ + 1280, sq_ + 1280);
    // d2
    deco(1, 192, 128, 128, 64, Wc + W2OFF, A_, S2,
         g_d1_, b_d1_, sum_ + 1280, sq_ + 1280, 1.0f / 12288.f,
         B_, sum_ + 1536, sq_ + 1536);
    // d3
    deco(0, 768, 64, 64, 32, Wc + W3OFF, B_, S3,
         g_d2_, b_d2_, sum_ + 1536, sq_ + 1536, 1.0f / 49152.f,
         A_, sum_ + 1792, sq_ + 1792);

    // -------- out layer (32 -> 1), BN(d3) fused into projection --------
    {
        int M = 196608;
        size_t PS = (size_t)M;
        proj4_k<<<(M * 32 + 255) / 256, 256>>>(A_, Wc + W4OFF, Z_, M, PS,
            g_d3_, b_d3_, 1.0f / 196608.f, sum_ + 1792, sq_ + 1792);
        spmm1(0, 768, 1, Z_,          Z_ + PS,     1.f, 1.f, Z_ + PS, nullptr, nullptr, 0);
        spmm1(0, 768, 1, Z_ + PS,     Z_ + 2 * PS, 1.f, 1.f, Z_ + 2 * PS, nullptr, nullptr, 0);
        spmm1(0, 768, 1, Z_ + 2 * PS, B_,          1.f, 1.f, Z_ + 3 * PS, nullptr, nullptr, 0);
    }
    reshape_out_k<<<196608 / 256, 256>>>(B_, (float*)d_out);
}